// round 7
// baseline (speedup 1.0000x reference)
#include <cuda_runtime.h>
#include <cstdint>
#include <cstddef>

// Problem constants
constexpr int N_NODES = 8192;
constexpr int C_DIM   = 16;

// Tiling
constexpr int TPB = 256;                 // threads per block
constexpr int CPT = 2;                   // columns per thread (one LDG.64)
constexpr int CPB = TPB * CPT;           // 512 columns per block
constexpr int RPB = 64;                  // rows per block
constexpr int GX  = N_NODES / CPB;       // 16
constexpr int GY  = N_NODES / RPB;       // 128
constexpr int NBLK = GX * GY;            // 2048
constexpr int PD  = 2;                   // prefetch distance (batches of 4 rows)
constexpr int NB  = RPB / 4;             // 16 batches

// partials layout per block: [0]=quad, [1]=s, [2..17]=dH[16]
__device__ float g_part[NBLK][18];
__device__ unsigned int g_done = 0;      // wraps back to 0 via atomicInc

__device__ __forceinline__ void unpack2(unsigned long long v, float& x, float& y) {
    asm("mov.b64 {%0, %1}, %2;" : "=f"(x), "=f"(y) : "l"(v));
}

// Guarded accumulate: if (a > 0) { cnt += 1; w[c] += h[c] (packed f32x2 x8) }
// One FSETP + 9 predicated instructions; no mask materialization, no multiply.
__device__ __forceinline__ void cond_acc(float a, const unsigned long long* h,
                                         unsigned long long* w, float& cnt) {
    asm volatile(
        "{\n\t"
        ".reg .pred p;\n\t"
        "setp.gt.f32 p, %18, 0f00000000;\n\t"
        "@p add.f32 %8, %8, 0f3F800000;\n\t"
        "@p add.rn.f32x2 %0, %0, %9;\n\t"
        "@p add.rn.f32x2 %1, %1, %10;\n\t"
        "@p add.rn.f32x2 %2, %2, %11;\n\t"
        "@p add.rn.f32x2 %3, %3, %12;\n\t"
        "@p add.rn.f32x2 %4, %4, %13;\n\t"
        "@p add.rn.f32x2 %5, %5, %14;\n\t"
        "@p add.rn.f32x2 %6, %6, %15;\n\t"
        "@p add.rn.f32x2 %7, %7, %16;\n\t"
        "}\n\t"
        : "+l"(w[0]), "+l"(w[1]), "+l"(w[2]), "+l"(w[3]),
          "+l"(w[4]), "+l"(w[5]), "+l"(w[6]), "+l"(w[7]),
          "+f"(cnt)
        : "l"(h[0]), "l"(h[1]), "l"(h[2]), "l"(h[3]),
          "l"(h[4]), "l"(h[5]), "l"(h[6]), "l"(h[7]),
          "f"(0.f),  // %17 unused pad (keeps numbering)
          "f"(a));
}

__global__ void __launch_bounds__(TPB, 3)
modmax_fused(const float* __restrict__ A, const float* __restrict__ H,
             float* __restrict__ out) {
    __shared__ __align__(16) float sH[RPB * C_DIM];   // 4 KB: H rows for this chunk

    const int tid  = threadIdx.x;
    const int bid  = blockIdx.y * GX + blockIdx.x;
    const int row0 = blockIdx.y * RPB;
    const int col0 = blockIdx.x * CPB + tid * CPT;

    // Stage H[row0 : row0+RPB][0:16] into smem (64*16 floats = 256 float4)
    {
        const float4* src = (const float4*)(H + (size_t)row0 * C_DIM);
        ((float4*)sH)[tid] = src[tid];
    }
    __syncthreads();

    // Accumulators: w[q][c] = sum_i adj[i][j_q] * H[i][2c:2c+2]
    unsigned long long w[CPT][8];
    #pragma unroll
    for (int q = 0; q < CPT; q++)
        #pragma unroll
        for (int c = 0; c < 8; c++) w[q][c] = 0ULL;
    float cnt[CPT] = {0.f, 0.f};

    const float2* Aeff = (const float2*)(A + (size_t)row0 * N_NODES + col0);
    const size_t rowStride2 = N_NODES / 2;

    // Software pipeline: PD batches of 4 rows (8 LDG.64 in flight per thread)
    float2 abuf[PD][4];
    #pragma unroll
    for (int p = 0; p < PD; p++)
        #pragma unroll
        for (int k = 0; k < 4; k++)
            abuf[p][k] = __ldg(Aeff + (size_t)(p * 4 + k) * rowStride2);

    #pragma unroll 1
    for (int it = 0; it < NB; it += PD) {
        #pragma unroll
        for (int p = 0; p < PD; p++) {
            const int b = it + p;                 // batch index
            // Consume abuf[p] in place (predicates extracted per row), then refill.
            #pragma unroll
            for (int k = 0; k < 4; k++) {
                const int ii = b * 4 + k;
                // H[ii] as 8 packed f32x2 (broadcast LDS.128 x4, conflict-free)
                const ulonglong2* sh = (const ulonglong2*)(sH + ii * C_DIM);
                ulonglong2 p0 = sh[0], p1 = sh[1], p2 = sh[2], p3 = sh[3];
                unsigned long long h[8] = {p0.x, p0.y, p1.x, p1.y,
                                           p2.x, p2.y, p3.x, p3.y};
                cond_acc(abuf[p][k].x, h, w[0], cnt[0]);
                cond_acc(abuf[p][k].y, h, w[1], cnt[1]);
            }
            if (b + PD < NB) {
                #pragma unroll
                for (int k = 0; k < 4; k++)
                    abuf[p][k] = __ldg(Aeff + (size_t)((b + PD) * 4 + k) * rowStride2);
            }
        }
    }

    // Epilogue: per-thread quad / dH / s contributions
    float quad_t = 0.f, s_t = 0.f;
    float dh_t[C_DIM];
    #pragma unroll
    for (int c = 0; c < C_DIM; c++) dh_t[c] = 0.f;

    #pragma unroll
    for (int q = 0; q < CPT; q++) {
        const float4* Hj4 = (const float4*)(H + (size_t)(col0 + q) * C_DIM);
        float hj[C_DIM];
        #pragma unroll
        for (int c4 = 0; c4 < 4; c4++) {
            float4 v = __ldg(Hj4 + c4);
            hj[4*c4+0] = v.x; hj[4*c4+1] = v.y; hj[4*c4+2] = v.z; hj[4*c4+3] = v.w;
        }
        #pragma unroll
        for (int c = 0; c < 8; c++) {
            float lo, hi; unpack2(w[q][c], lo, hi);
            quad_t += hj[2*c] * lo + hj[2*c+1] * hi;
        }
        #pragma unroll
        for (int c = 0; c < C_DIM; c++) dh_t[c] += cnt[q] * hj[c];
        s_t += cnt[q];
    }

    // Warp-level reduction of 18 values
    #pragma unroll
    for (int off = 16; off > 0; off >>= 1) {
        quad_t += __shfl_xor_sync(0xffffffffu, quad_t, off);
        s_t    += __shfl_xor_sync(0xffffffffu, s_t, off);
        #pragma unroll
        for (int c = 0; c < C_DIM; c++)
            dh_t[c] += __shfl_xor_sync(0xffffffffu, dh_t[c], off);
    }

    __shared__ float sred[TPB / 32][18];
    const int warp = tid >> 5, lane = tid & 31;
    if (lane == 0) {
        sred[warp][0] = quad_t;
        sred[warp][1] = s_t;
        #pragma unroll
        for (int c = 0; c < C_DIM; c++) sred[warp][2 + c] = dh_t[c];
    }
    __syncthreads();
    if (tid < 18) {
        float v = 0.f;
        #pragma unroll
        for (int wd = 0; wd < TPB / 32; wd++) v += sred[wd][tid];
        g_part[bid][tid] = v;
    }

    // ---- fused final reduction: last block to finish does it ----
    __threadfence();                      // make g_part[bid] globally visible
    __syncthreads();
    __shared__ bool isLast;
    if (tid == 0) {
        unsigned old = atomicInc(&g_done, NBLK - 1);   // wraps to 0 -> self-reset
        isLast = (old == NBLK - 1);
    }
    __syncthreads();
    if (!isLast) return;

    __threadfence();                      // acquire: other blocks' partials
    __shared__ float comp[18];
    // 8 warps: warp w reduces components w, w+8, (w+16)
    for (int c = warp; c < 18; c += TPB / 32) {
        float v = 0.f;
        #pragma unroll
        for (int i = 0; i < NBLK / 32; i++) v += g_part[lane + 32 * i][c];
        #pragma unroll
        for (int off = 16; off > 0; off >>= 1)
            v += __shfl_xor_sync(0xffffffffu, v, off);
        if (lane == 0) comp[c] = v;
    }
    __syncthreads();
    if (tid == 0) {
        float quad = comp[0], s = comp[1];
        float dd = 0.f;
        #pragma unroll
        for (int c = 0; c < C_DIM; c++) dd += comp[2 + c] * comp[2 + c];
        out[0] = (quad - dd / s) / s;
    }
}

extern "C" void kernel_launch(void* const* d_in, const int* in_sizes, int n_in,
                              void* d_out, int out_size) {
    const float* H = (const float*)d_in[0];
    const float* A = (const float*)d_in[1];
    // Defensive: pick by size (H is N*C, A is N*N)
    if (in_sizes[0] != N_NODES * C_DIM) { const float* t = H; H = A; A = t; }

    dim3 grid(GX, GY);
    modmax_fused<<<grid, TPB>>>(A, H, (float*)d_out);
}

// round 10
// speedup vs baseline: 1.3804x; 1.3804x over previous
#include <cuda_runtime.h>
#include <cstdint>
#include <cstddef>

// Problem constants
constexpr int N_NODES = 8192;
constexpr int C_DIM   = 16;

// Tiling
constexpr int TPB = 256;                 // threads per block
constexpr int CPT = 2;                   // columns per thread (one LDG.64)
constexpr int CPB = TPB * CPT;           // 512 columns per block
constexpr int RPB = 64;                  // rows per block
constexpr int GX  = N_NODES / CPB;       // 16
constexpr int GY  = N_NODES / RPB;       // 128
constexpr int NBLK = GX * GY;            // 2048
constexpr int PD  = 2;                   // prefetch distance (batches of 4 rows)
constexpr int NB  = RPB / 4;             // 16 batches

// partials layout per block: [0]=quad, [1]=s, [2..17]=dH[16]
__device__ float g_part[NBLK][18];
__device__ unsigned int g_done = 0;      // wraps back to 0 via atomicInc

__device__ __forceinline__ unsigned long long pack2(float x, float y) {
    unsigned long long r;
    asm("mov.b64 %0, {%1, %2};" : "=l"(r) : "f"(x), "f"(y));
    return r;
}
__device__ __forceinline__ void unpack2(unsigned long long v, float& x, float& y) {
    asm("mov.b64 {%0, %1}, %2;" : "=f"(x), "=f"(y) : "l"(v));
}
// packed fp32x2 FMA (Blackwell sm_10x, FMA pipe): d = a*b + c on two lanes
__device__ __forceinline__ unsigned long long fma2(unsigned long long a,
                                                   unsigned long long b,
                                                   unsigned long long c) {
    unsigned long long d;
    asm("fma.rn.f32x2 %0, %1, %2, %3;" : "=l"(d) : "l"(a), "l"(b), "l"(c));
    return d;
}

__global__ void __launch_bounds__(TPB, 3)
modmax_fused(const float* __restrict__ A, const float* __restrict__ H,
             float* __restrict__ out) {
    __shared__ __align__(16) float sH[RPB * C_DIM];   // 4 KB: H rows for this chunk

    const int tid  = threadIdx.x;
    const int bid  = blockIdx.y * GX + blockIdx.x;
    const int row0 = blockIdx.y * RPB;
    const int col0 = blockIdx.x * CPB + tid * CPT;

    // Stage H[row0 : row0+RPB][0:16] into smem (64*16 floats = 256 float4)
    {
        const float4* src = (const float4*)(H + (size_t)row0 * C_DIM);
        ((float4*)sH)[tid] = src[tid];
    }
    __syncthreads();

    // Accumulators: w[q][c] = sum_i adj[i][j_q] * H[i][2c:2c+2]
    unsigned long long w[CPT][8];
    #pragma unroll
    for (int q = 0; q < CPT; q++)
        #pragma unroll
        for (int c = 0; c < 8; c++) w[q][c] = 0ULL;
    float cnt[CPT] = {0.f, 0.f};

    const float2* Aeff = (const float2*)(A + (size_t)row0 * N_NODES + col0);
    const size_t rowStride2 = N_NODES / 2;

    // Software pipeline: PD batches of 4 rows (8 LDG.64 in flight per thread)
    float2 abuf[PD][4];
    #pragma unroll
    for (int p = 0; p < PD; p++)
        #pragma unroll
        for (int k = 0; k < 4; k++)
            abuf[p][k] = __ldg(Aeff + (size_t)(p * 4 + k) * rowStride2);

    #pragma unroll 1
    for (int it = 0; it < NB; it += PD) {
        #pragma unroll
        for (int p = 0; p < PD; p++) {
            const int b = it + p;                 // batch index
            // Consume abuf[p] in place, then refill for batch b+PD.
            #pragma unroll
            for (int k = 0; k < 4; k++) {
                const int ii = b * 4 + k;
                // H[ii] as 8 packed f32x2 (broadcast LDS.128 x4, conflict-free)
                const ulonglong2* sh = (const ulonglong2*)(sH + ii * C_DIM);
                ulonglong2 p0 = sh[0], p1 = sh[1], p2 = sh[2], p3 = sh[3];
                unsigned long long h[8] = {p0.x, p0.y, p1.x, p1.y,
                                           p2.x, p2.y, p3.x, p3.y};

                float2 a = abuf[p][k];
                float m0 = a.x > 0.f ? 1.f : 0.f;
                float m1 = a.y > 0.f ? 1.f : 0.f;
                cnt[0] += m0; cnt[1] += m1;
                unsigned long long mm[2] = {pack2(m0, m0), pack2(m1, m1)};
                #pragma unroll
                for (int q = 0; q < CPT; q++)
                    #pragma unroll
                    for (int c = 0; c < 8; c++)
                        w[q][c] = fma2(mm[q], h[c], w[q][c]);
            }
            if (b + PD < NB) {
                #pragma unroll
                for (int k = 0; k < 4; k++)
                    abuf[p][k] = __ldg(Aeff + (size_t)((b + PD) * 4 + k) * rowStride2);
            }
        }
    }

    // Epilogue: per-thread quad / dH / s contributions
    float quad_t = 0.f, s_t = 0.f;
    float dh_t[C_DIM];
    #pragma unroll
    for (int c = 0; c < C_DIM; c++) dh_t[c] = 0.f;

    #pragma unroll
    for (int q = 0; q < CPT; q++) {
        const float4* Hj4 = (const float4*)(H + (size_t)(col0 + q) * C_DIM);
        float hj[C_DIM];
        #pragma unroll
        for (int c4 = 0; c4 < 4; c4++) {
            float4 v = __ldg(Hj4 + c4);
            hj[4*c4+0] = v.x; hj[4*c4+1] = v.y; hj[4*c4+2] = v.z; hj[4*c4+3] = v.w;
        }
        #pragma unroll
        for (int c = 0; c < 8; c++) {
            float lo, hi; unpack2(w[q][c], lo, hi);
            quad_t += hj[2*c] * lo + hj[2*c+1] * hi;
        }
        #pragma unroll
        for (int c = 0; c < C_DIM; c++) dh_t[c] += cnt[q] * hj[c];
        s_t += cnt[q];
    }

    // Warp-level reduction of 18 values
    #pragma unroll
    for (int off = 16; off > 0; off >>= 1) {
        quad_t += __shfl_xor_sync(0xffffffffu, quad_t, off);
        s_t    += __shfl_xor_sync(0xffffffffu, s_t, off);
        #pragma unroll
        for (int c = 0; c < C_DIM; c++)
            dh_t[c] += __shfl_xor_sync(0xffffffffu, dh_t[c], off);
    }

    __shared__ float sred[TPB / 32][18];
    const int warp = tid >> 5, lane = tid & 31;
    if (lane == 0) {
        sred[warp][0] = quad_t;
        sred[warp][1] = s_t;
        #pragma unroll
        for (int c = 0; c < C_DIM; c++) sred[warp][2 + c] = dh_t[c];
    }
    __syncthreads();
    if (tid < 18) {
        float v = 0.f;
        #pragma unroll
        for (int wd = 0; wd < TPB / 32; wd++) v += sred[wd][tid];
        g_part[bid][tid] = v;
    }

    // ---- fused final reduction: last block to finish does it ----
    __threadfence();                      // make g_part[bid] globally visible
    __syncthreads();
    __shared__ bool isLast;
    if (tid == 0) {
        unsigned old = atomicInc(&g_done, NBLK - 1);   // wraps to 0 -> self-reset
        isLast = (old == NBLK - 1);
    }
    __syncthreads();
    if (!isLast) return;

    __threadfence();                      // acquire: other blocks' partials
    __shared__ float comp[18];
    // 8 warps: warp w reduces components w, w+8, (w+16)
    for (int c = warp; c < 18; c += TPB / 32) {
        float v = 0.f;
        #pragma unroll
        for (int i = 0; i < NBLK / 32; i++) v += g_part[lane + 32 * i][c];
        #pragma unroll
        for (int off = 16; off > 0; off >>= 1)
            v += __shfl_xor_sync(0xffffffffu, v, off);
        if (lane == 0) comp[c] = v;
    }
    __syncthreads();
    if (tid == 0) {
        float quad = comp[0], s = comp[1];
        float dd = 0.f;
        #pragma unroll
        for (int c = 0; c < C_DIM; c++) dd += comp[2 + c] * comp[2 + c];
        out[0] = (quad - dd / s) / s;
    }
}

extern "C" void kernel_launch(void* const* d_in, const int* in_sizes, int n_in,
                              void* d_out, int out_size) {
    const float* H = (const float*)d_in[0];
    const float* A = (const float*)d_in[1];
    // Defensive: pick by size (H is N*C, A is N*N)
    if (in_sizes[0] != N_NODES * C_DIM) { const float* t = H; H = A; A = t; }

    dim3 grid(GX, GY);
    modmax_fused<<<grid, TPB>>>(A, H, (float*)d_out);
}